// round 1
// baseline (speedup 1.0000x reference)
#include <cuda_runtime.h>

// Kuramoto oscillator network, B=32 batches, N=2048 oscillators, K=8 neighbors, T=20 steps.
// One CTA per batch element; phases live in double-buffered shared memory.
// delta = eps * (Cs*cos - Cc*sin)/n  ==  (1/n) * sum_k C_k * sin(theta_m - theta_n)
// Duplicate scatter targets: LAST k wins (XLA CPU scatter order); n = #distinct nonzero targets.

#define Nn 2048
#define Kk 8
#define Bb 32
#define Tt 20
#define THREADS 512
#define OPT (Nn / THREADS)   // oscillators per thread = 4

#define TWO_PI     6.28318530717958647692f
#define INV_TWO_PI 0.15915494309189533577f

__global__ void __launch_bounds__(THREADS, 1)
osc_kernel(const float* __restrict__ coupling,   // [B,N,K]
           const float* __restrict__ phase0,     // [B,N]
           const float* __restrict__ omega,      // [B,N]
           const int*   __restrict__ conn,       // [N,K]
           float*       __restrict__ out)        // [T+1,B,N]
{
    __shared__ float th[2][Nn];   // range-reduced phases, double buffered

    const int b   = blockIdx.x;
    const int tid = threadIdx.x;

    float w[OPT][Kk];     // effective (dedup'd) couplings
    int   off[OPT][Kk];   // neighbor indices
    float phase[OPT];     // exact phase (for output)
    float inv[OPT];       // eps / n  (eps == 1, anneal == 0)
    float om[OPT];

    // ---- one-time prologue: winner mask + count, load phase0/omega ----
    #pragma unroll
    for (int j = 0; j < OPT; ++j) {
        const int n = tid + j * THREADS;
        int idx[Kk];
        #pragma unroll
        for (int k = 0; k < Kk; ++k) idx[k] = conn[n * Kk + k];

        int cnt = 0;
        #pragma unroll
        for (int k = 0; k < Kk; ++k) {
            // k survives the scatter iff no later k' writes the same target
            bool win = true;
            #pragma unroll
            for (int k2 = k + 1; k2 < Kk; ++k2) win = win && (idx[k2] != idx[k]);
            const float c = coupling[((size_t)b * Nn + n) * Kk + k];
            w[j][k]  = win ? c : 0.0f;
            off[j][k] = idx[k];
            cnt += (win && (c != 0.0f)) ? 1 : 0;
        }
        inv[j]  = (cnt > 0) ? (1.0f / (float)cnt) : 0.0f;

        const float p = phase0[b * Nn + n];
        phase[j] = p;
        om[j]    = omega[b * Nn + n];

        // t = 0 output slice is the initial phase
        out[(size_t)b * Nn + n] = p;

        // range-reduced copy for the sin() of differences (2*pi periodic)
        th[0][n] = p - TWO_PI * rintf(p * INV_TWO_PI);
    }
    __syncthreads();

    // ---- time stepping: 1 barrier per step via double buffering ----
    #pragma unroll 1
    for (int t = 0; t < Tt; ++t) {
        const float* __restrict__ cur = th[t & 1];
        float*       __restrict__ nxt = th[(t + 1) & 1];

        #pragma unroll
        for (int j = 0; j < OPT; ++j) {
            const int n = tid + j * THREADS;
            const float pr = cur[n];   // own reduced phase (same value we stored)

            float acc = 0.0f;
            #pragma unroll
            for (int k = 0; k < Kk; ++k) {
                const float pm = cur[off[j][k]];
                acc += w[j][k] * __sinf(pm - pr);   // arg in [-2pi, 2pi]
            }

            float p = phase[j] + acc * inv[j] + om[j];
            phase[j] = p;

            nxt[n] = p - TWO_PI * rintf(p * INV_TWO_PI);
            out[(size_t)(t + 1) * (Bb * Nn) + (size_t)b * Nn + n] = p;
        }
        __syncthreads();
    }
}

extern "C" void kernel_launch(void* const* d_in, const int* in_sizes, int n_in,
                              void* d_out, int out_size)
{
    const float* coupling = (const float*)d_in[0];   // [B,N,K] f32
    const float* phase0   = (const float*)d_in[1];   // [B,N]   f32
    const float* omega    = (const float*)d_in[2];   // [B,N]   f32
    const int*   conn     = (const int*)  d_in[3];   // [N,K]   i32
    float*       out      = (float*)d_out;           // [T+1,B,N] f32

    osc_kernel<<<Bb, THREADS>>>(coupling, phase0, omega, conn, out);
}

// round 2
// speedup vs baseline: 1.4110x; 1.4110x over previous
#include <cuda_runtime.h>
#include <cstdint>

// Kuramoto oscillator network: B=32, N=2048, K=8, T=20.
// R2: cluster of 4 CTAs per batch element (grid=128 -> ~128 SMs active vs 32).
// Each CTA holds a full replicated phase array in smem; computes N/4=512
// oscillators per step; broadcasts its slice to the 3 peers via DSMEM
// (mapa + st.shared::cluster); one cluster barrier per step (double-buffered).
// Duplicate scatter targets: LAST k wins; n = #distinct nonzero targets.

#define Nn 2048
#define Kk 8
#define Bb 32
#define Tt 20
#define CSZ 4                  // cluster size (CTAs per batch element)
#define THREADS 512
#define NPC (Nn / CSZ)         // oscillators per CTA = 512 (1 per thread)

#define TWO_PI     6.28318530717958647692f
#define INV_TWO_PI 0.15915494309189533577f

__device__ __forceinline__ uint32_t smem_u32(const void* p) {
    uint32_t a;
    asm("{ .reg .u64 t; cvta.to.shared.u64 t, %1; cvt.u32.u64 %0, t; }"
        : "=r"(a) : "l"(p));
    return a;
}

__device__ __forceinline__ void st_shared_cluster_f32(uint32_t local_addr,
                                                      uint32_t target_rank,
                                                      float v) {
    asm volatile(
        "{ .reg .b32 r; mapa.shared::cluster.u32 r, %0, %1; "
        "st.shared::cluster.f32 [r], %2; }"
        :: "r"(local_addr), "r"(target_rank), "f"(v) : "memory");
}

__global__ void __launch_bounds__(THREADS, 1) __cluster_dims__(CSZ, 1, 1)
osc_kernel(const float* __restrict__ coupling,   // [B,N,K]
           const float* __restrict__ phase0,     // [B,N]
           const float* __restrict__ omega,      // [B,N]
           const int*   __restrict__ conn,       // [N,K]
           float*       __restrict__ out)        // [T+1,B,N]
{
    __shared__ float th[2][Nn];   // full replicated, range-reduced phases

    uint32_t rank;
    asm("mov.u32 %0, %%cluster_ctarank;" : "=r"(rank));
    const int b   = blockIdx.x / CSZ;
    const int tid = threadIdx.x;
    const int n   = (int)rank * NPC + tid;   // this thread's oscillator

    // ---- prologue: dedup couplings for oscillator n ----
    float w[Kk];
    int   off[Kk];
    int idx[Kk];
    #pragma unroll
    for (int k = 0; k < Kk; ++k) idx[k] = conn[n * Kk + k];

    int cnt = 0;
    #pragma unroll
    for (int k = 0; k < Kk; ++k) {
        bool win = true;
        #pragma unroll
        for (int k2 = k + 1; k2 < Kk; ++k2) win = win && (idx[k2] != idx[k]);
        const float c = coupling[((size_t)b * Nn + n) * Kk + k];
        w[k]   = win ? c : 0.0f;
        off[k] = idx[k];
        cnt += (win && (c != 0.0f)) ? 1 : 0;
    }
    const float inv = (cnt > 0) ? (1.0f / (float)cnt) : 0.0f;

    float p  = phase0[(size_t)b * Nn + n];
    const float om = omega[(size_t)b * Nn + n];

    // t=0 output slice (each rank writes its own 512)
    out[(size_t)b * Nn + n] = p;

    // every CTA fills its FULL th[0] copy from gmem (4 per thread)
    #pragma unroll
    for (int j = 0; j < CSZ; ++j) {
        const int m  = tid + j * THREADS;
        const float q = phase0[(size_t)b * Nn + m];
        th[0][m] = q - TWO_PI * rintf(q * INV_TWO_PI);
    }
    float pr = p - TWO_PI * rintf(p * INV_TWO_PI);   // own reduced phase
    __syncthreads();   // local copy complete; no cross-CTA dependence yet

    // ---- time stepping: one cluster barrier per step ----
    #pragma unroll 1
    for (int t = 0; t < Tt; ++t) {
        const float* __restrict__ cur = th[t & 1];

        float acc = 0.0f;
        #pragma unroll
        for (int k = 0; k < Kk; ++k) {
            acc += w[k] * __sinf(cur[off[k]] - pr);   // arg in [-2pi, 2pi]
        }

        p = p + acc * inv + om;
        const float prn = p - TWO_PI * rintf(p * INV_TWO_PI);
        pr = prn;

        // write reduced phase into all 4 CTAs' next buffer
        float* nxt = th[(t + 1) & 1];
        nxt[n] = prn;                                  // own copy (plain STS)
        const uint32_t laddr = smem_u32(&nxt[n]);
        #pragma unroll
        for (int r = 0; r < CSZ; ++r) {
            if ((uint32_t)r != rank)
                st_shared_cluster_f32(laddr, (uint32_t)r, prn);
        }

        // arrive early, hide the global store behind the barrier wait
        asm volatile("barrier.cluster.arrive.aligned;" ::: "memory");
        out[(size_t)(t + 1) * (Bb * Nn) + (size_t)b * Nn + n] = p;
        asm volatile("barrier.cluster.wait.aligned;" ::: "memory");
    }
}

extern "C" void kernel_launch(void* const* d_in, const int* in_sizes, int n_in,
                              void* d_out, int out_size)
{
    const float* coupling = (const float*)d_in[0];   // [B,N,K] f32
    const float* phase0   = (const float*)d_in[1];   // [B,N]   f32
    const float* omega    = (const float*)d_in[2];   // [B,N]   f32
    const int*   conn     = (const int*)  d_in[3];   // [N,K]   i32
    float*       out      = (float*)d_out;           // [T+1,B,N] f32

    osc_kernel<<<Bb * CSZ, THREADS>>>(coupling, phase0, omega, conn, out);
}